// round 1
// baseline (speedup 1.0000x reference)
#include <cuda_runtime.h>
#include <math.h>

#define NN 50000
#define EE 800000
#define DD 64
#define HH 8

// ---------------- scratch (static device globals; no allocation) ----------------
__device__ float g_h[NN * DD];      // node features (ping)
__device__ float g_hp[NN * DD];     // projected features per layer
__device__ float g_ai[NN * HH];     // per-node att dot, dst half
__device__ float g_aj[NN * HH];     // per-node att dot, src half
__device__ int   g_deg[NN];
__device__ int   g_rowptr[NN + 1];
__device__ int   g_cursor[NN];
__device__ int   g_csrc[EE];        // CSR-by-dst: source node per slot
__device__ int   g_bsum[64];

// ---------------- CSR build ----------------
__global__ void k_zero_deg() {
    int i = blockIdx.x * blockDim.x + threadIdx.x;
    if (i < NN) g_deg[i] = 0;
}

__global__ void k_hist(const int* __restrict__ dst) {
    int e = blockIdx.x * blockDim.x + threadIdx.x;
    if (e < EE) atomicAdd(&g_deg[dst[e]], 1);
}

__global__ void k_scan1() {
    __shared__ int ws[32];
    int i = blockIdx.x * 1024 + threadIdx.x;
    int lane = threadIdx.x & 31, w = threadIdx.x >> 5;
    int x = (i < NN) ? g_deg[i] : 0;
    int v = x;
#pragma unroll
    for (int o = 1; o < 32; o <<= 1) {
        int t = __shfl_up_sync(0xffffffffu, v, o);
        if (lane >= o) v += t;
    }
    if (lane == 31) ws[w] = v;
    __syncthreads();
    if (w == 0) {
        int t = ws[lane];
#pragma unroll
        for (int o = 1; o < 32; o <<= 1) {
            int u = __shfl_up_sync(0xffffffffu, t, o);
            if (lane >= o) t += u;
        }
        ws[lane] = t;
    }
    __syncthreads();
    int off = (w > 0) ? ws[w - 1] : 0;
    int incl = v + off;
    if (i < NN) g_rowptr[i] = incl - x;           // exclusive within block
    if (threadIdx.x == 1023) g_bsum[blockIdx.x] = incl;
}

__global__ void k_scan2(int nb) {
    int acc = 0;
    for (int i = 0; i < nb; i++) { int t = g_bsum[i]; g_bsum[i] = acc; acc += t; }
}

__global__ void k_scan3() {
    int i = blockIdx.x * blockDim.x + threadIdx.x;
    if (i < NN) {
        int r = g_rowptr[i] + g_bsum[i >> 10];
        g_rowptr[i] = r;
        g_cursor[i] = r;
    }
    if (i == 0) g_rowptr[NN] = EE;
}

__global__ void k_scatter(const int* __restrict__ src, const int* __restrict__ dst) {
    int e = blockIdx.x * blockDim.x + threadIdx.x;
    if (e < EE) {
        int pos = atomicAdd(&g_cursor[dst[e]], 1);
        g_csrc[pos] = src[e];
    }
}

// ---------------- GEMM: C[N,64] = A[N,64] @ W[64,64] + bias (opt relu) ----------------
// 64x64 tile per 128-thread block; thread tile 8 rows x 4 cols; k in float4 steps.
__global__ void __launch_bounds__(128) k_gemm(const float* __restrict__ A,
                                              const float* __restrict__ W,
                                              const float* __restrict__ bias,
                                              float* __restrict__ C, int do_relu) {
    __shared__ float As[64 * 64];
    __shared__ float Bs[64 * 64];
    int tid = threadIdx.x;
    int base = blockIdx.x * 64;
#pragma unroll
    for (int i = 0; i < 8; i++) {
        int idx = tid + i * 128;
        int r = idx >> 4, c4 = (idx & 15) << 2;
        float4 v = make_float4(0.f, 0.f, 0.f, 0.f);
        if (base + r < NN) v = *(const float4*)(A + (size_t)(base + r) * 64 + c4);
        *(float4*)(As + r * 64 + c4) = v;
        *(float4*)(Bs + r * 64 + c4) = *(const float4*)(W + r * 64 + c4);
    }
    __syncthreads();
    int tx = tid & 15, ty = tid >> 4;
    int n0 = tx * 4, m0 = ty * 8;
    float acc[8][4];
#pragma unroll
    for (int i = 0; i < 8; i++) { acc[i][0] = 0.f; acc[i][1] = 0.f; acc[i][2] = 0.f; acc[i][3] = 0.f; }
#pragma unroll 2
    for (int k4 = 0; k4 < 16; k4++) {
        float4 b0 = *(float4*)(Bs + (k4 * 4 + 0) * 64 + n0);
        float4 b1 = *(float4*)(Bs + (k4 * 4 + 1) * 64 + n0);
        float4 b2 = *(float4*)(Bs + (k4 * 4 + 2) * 64 + n0);
        float4 b3 = *(float4*)(Bs + (k4 * 4 + 3) * 64 + n0);
#pragma unroll
        for (int i = 0; i < 8; i++) {
            float4 a = *(float4*)(As + (m0 + i) * 64 + k4 * 4);
            acc[i][0] += a.x * b0.x + a.y * b1.x + a.z * b2.x + a.w * b3.x;
            acc[i][1] += a.x * b0.y + a.y * b1.y + a.z * b2.y + a.w * b3.y;
            acc[i][2] += a.x * b0.z + a.y * b1.z + a.z * b2.z + a.w * b3.z;
            acc[i][3] += a.x * b0.w + a.y * b1.w + a.z * b2.w + a.w * b3.w;
        }
    }
    float4 bb = *(const float4*)(bias + n0);
#pragma unroll
    for (int i = 0; i < 8; i++) {
        int r = base + m0 + i;
        if (r < NN) {
            float4 o;
            o.x = acc[i][0] + bb.x;
            o.y = acc[i][1] + bb.y;
            o.z = acc[i][2] + bb.z;
            o.w = acc[i][3] + bb.w;
            if (do_relu) {
                o.x = fmaxf(o.x, 0.f); o.y = fmaxf(o.y, 0.f);
                o.z = fmaxf(o.z, 0.f); o.w = fmaxf(o.w, 0.f);
            }
            *(float4*)(C + (size_t)r * 64 + n0) = o;
        }
    }
}

// ---------------- per-node attention dot products ----------------
// ai[n,h] = hp[n,h,:].att[h,:C]   aj[n,h] = hp[n,h,:].att[h,C:]
__global__ void k_attdot(const float* __restrict__ att) {
    int idx = blockIdx.x * blockDim.x + threadIdx.x;
    if (idx >= NN * HH) return;
    int n = idx >> 3, h = idx & 7;
    const float4* p = (const float4*)(g_hp + (size_t)n * 64 + h * 8);
    float4 p0 = p[0], p1 = p[1];
    const float4* a4 = (const float4*)(att + h * 16);
    float4 a0 = a4[0], a1 = a4[1], a2 = a4[2], a3 = a4[3];
    g_ai[idx] = p0.x * a0.x + p0.y * a0.y + p0.z * a0.z + p0.w * a0.w +
                p1.x * a1.x + p1.y * a1.y + p1.z * a1.z + p1.w * a1.w;
    g_aj[idx] = p0.x * a2.x + p0.y * a2.y + p0.z * a2.z + p0.w * a2.w +
                p1.x * a3.x + p1.y * a3.y + p1.z * a3.z + p1.w * a3.w;
}

// ---------------- fused edge softmax + aggregation + ELU + LayerNorm ----------------
// One warp per destination node. Lane l owns feature cols (2l, 2l+1), head h = l>>2.
// Pass 1: per-head max over incoming edges. Pass 2: exp-sum + weighted feature agg.
// Then ELU + LayerNorm via warp shuffle reductions.
__global__ void __launch_bounds__(256) k_edge(const float* __restrict__ ob,
                                              const float* __restrict__ lg,
                                              const float* __restrict__ lb,
                                              float* __restrict__ out) {
    int n = (blockIdx.x * blockDim.x + threadIdx.x) >> 5;
    int lane = threadIdx.x & 31;
    if (n >= NN) return;
    int e0 = g_rowptr[n], e1 = g_rowptr[n + 1];
    int h = lane >> 2;
    float aih = g_ai[n * 8 + h];

    float m = -1e30f;
    for (int e = e0; e < e1; e++) {
        int src = __ldg(&g_csrc[e]);
        float a = aih + __ldg(&g_aj[src * 8 + h]);
        a = fmaxf(a, 0.2f * a);               // leaky_relu(0.2)
        m = fmaxf(m, a);
    }

    float s = 0.f, ax = 0.f, ay = 0.f;
    const float2* hp2 = (const float2*)g_hp;
    for (int e = e0; e < e1; e++) {
        int src = __ldg(&g_csrc[e]);
        float a = aih + __ldg(&g_aj[src * 8 + h]);
        a = fmaxf(a, 0.2f * a);
        float ea = __expf(a - m);
        s += ea;
        float2 v = __ldg(&hp2[(size_t)src * 32 + lane]);
        ax += v.x * ea;
        ay += v.y * ea;
    }

    float inv = 1.f / (s + 1e-16f);
    float vx = ax * inv + ob[2 * lane];
    float vy = ay * inv + ob[2 * lane + 1];
    vx = vx > 0.f ? vx : expm1f(vx);          // ELU
    vy = vy > 0.f ? vy : expm1f(vy);

    float sum = vx + vy, sq = vx * vx + vy * vy;
#pragma unroll
    for (int o = 16; o > 0; o >>= 1) {
        sum += __shfl_xor_sync(0xffffffffu, sum, o);
        sq  += __shfl_xor_sync(0xffffffffu, sq, o);
    }
    float mu = sum * (1.f / 64.f);
    float var = sq * (1.f / 64.f) - mu * mu;
    float rstd = rsqrtf(var + 1e-5f);
    float2 o2;
    o2.x = (vx - mu) * rstd * lg[2 * lane] + lb[2 * lane];
    o2.y = (vy - mu) * rstd * lg[2 * lane + 1] + lb[2 * lane + 1];
    ((float2*)out)[(size_t)n * 32 + lane] = o2;
}

// ---------------- launch ----------------
extern "C" void kernel_launch(void* const* d_in, const int* in_sizes, int n_in,
                              void* d_out, int out_size) {
    const float* x        = (const float*)d_in[0];
    const int*   ei       = (const int*)  d_in[1];
    const float* W_in     = (const float*)d_in[2];
    const float* b_in     = (const float*)d_in[3];
    const float* lin_w    = (const float*)d_in[4];
    const float* lin_b    = (const float*)d_in[5];
    const float* att      = (const float*)d_in[6];
    const float* out_bias = (const float*)d_in[7];
    const float* ln_g     = (const float*)d_in[8];
    const float* ln_b     = (const float*)d_in[9];
    float* out = (float*)d_out;
    const int* srcp = ei;        // edge_index[0]
    const int* dstp = ei + EE;   // edge_index[1]

    void* p;
    cudaGetSymbolAddress(&p, g_h);  float* ph  = (float*)p;
    (void)n_in; (void)in_sizes; (void)out_size;

    // CSR by dst (indices are an input; rebuilt every call — cheap)
    k_zero_deg<<<(NN + 255) / 256, 256>>>();
    k_hist   <<<(EE + 255) / 256, 256>>>(dstp);
    k_scan1  <<<(NN + 1023) / 1024, 1024>>>();
    k_scan2  <<<1, 1>>>((NN + 1023) / 1024);
    k_scan3  <<<(NN + 255) / 256, 256>>>();
    k_scatter<<<(EE + 255) / 256, 256>>>(srcp, dstp);

    int gblocks = (NN + 63) / 64;
    // input embedding: h = relu(x @ W_in + b_in)
    k_gemm<<<gblocks, 128>>>(x, W_in, b_in, ph, 1);

    void* php_;
    cudaGetSymbolAddress(&php_, g_hp); float* php = (float*)php_;

    for (int l = 0; l < 5; l++) {
        k_gemm  <<<gblocks, 128>>>(ph, lin_w + l * 64 * 64, lin_b + l * 64, php, 0);
        k_attdot<<<(NN * 8 + 255) / 256, 256>>>(att + l * 128);
        k_edge  <<<(NN + 7) / 8, 256>>>(out_bias + l * 64, ln_g + l * 64, ln_b + l * 64,
                                        (l == 4) ? out : ph);
    }
}

// round 2
// speedup vs baseline: 1.7896x; 1.7896x over previous
#include <cuda_runtime.h>
#include <math.h>

#define NN 50000
#define EE 800000
#define DD 64
#define HH 8

// ---------------- scratch (static device globals; no allocation) ----------------
__device__ float g_h[NN * DD];      // node features (ping)
__device__ float g_hp[NN * DD];     // projected features per layer
__device__ float g_ai[NN * HH];     // per-node att dot, dst half
__device__ float g_aj[NN * HH];     // per-node att dot, src half
__device__ int   g_deg[NN];
__device__ int   g_rowptr[NN + 1];
__device__ int   g_cursor[NN];
__device__ int   g_csrc[EE];        // CSR-by-dst: source node per slot

// ---------------- CSR build ----------------
__global__ void k_hist(const int* __restrict__ dst) {
    int e = blockIdx.x * blockDim.x + threadIdx.x;
    if (e < EE) atomicAdd(&g_deg[dst[e]], 1);
}

// single-block exclusive scan of g_deg -> g_rowptr/g_cursor (50000 elems, 1024 thr)
__global__ void __launch_bounds__(1024) k_scan() {
    __shared__ int ws[32];
    __shared__ int carry_s;
    int lane = threadIdx.x & 31, w = threadIdx.x >> 5;
    if (threadIdx.x == 0) carry_s = 0;
    __syncthreads();
    for (int base = 0; base < NN; base += 1024) {
        int i = base + threadIdx.x;
        int x = (i < NN) ? g_deg[i] : 0;
        int v = x;
#pragma unroll
        for (int o = 1; o < 32; o <<= 1) {
            int t = __shfl_up_sync(0xffffffffu, v, o);
            if (lane >= o) v += t;
        }
        if (lane == 31) ws[w] = v;
        __syncthreads();
        if (w == 0) {
            int t = ws[lane];
#pragma unroll
            for (int o = 1; o < 32; o <<= 1) {
                int u = __shfl_up_sync(0xffffffffu, t, o);
                if (lane >= o) t += u;
            }
            ws[lane] = t;
        }
        __syncthreads();
        int off = (w > 0) ? ws[w - 1] : 0;
        int incl = v + off;
        int total = ws[31];
        int carry = carry_s;
        if (i < NN) {
            int r = incl - x + carry;
            g_rowptr[i] = r;
            g_cursor[i] = r;
        }
        __syncthreads();
        if (threadIdx.x == 0) carry_s = carry + total;
        __syncthreads();
    }
    if (threadIdx.x == 0) g_rowptr[NN] = EE;
}

__global__ void k_scatter(const int* __restrict__ src, const int* __restrict__ dst) {
    int e = blockIdx.x * blockDim.x + threadIdx.x;
    if (e < EE) {
        int pos = atomicAdd(&g_cursor[dst[e]], 1);
        g_csrc[pos] = src[e];
    }
}

// ---------------- GEMM: C[N,64] = A[N,64] @ W[64,64] + bias ----------------
// 64x64 tile per 128-thread block; thread tile 8 rows x 4 cols.
// Optional fused epilogues: relu (input embedding) or attention dot products
// (ai/aj per node-head) -- each thread's 4 cols lie inside one head; one
// shfl_xor(1) combines the two threads covering that head.
__global__ void __launch_bounds__(128) k_gemm(const float* __restrict__ A,
                                              const float* __restrict__ W,
                                              const float* __restrict__ bias,
                                              float* __restrict__ C, int do_relu,
                                              const float* __restrict__ att) {
    __shared__ float As[64 * 64];
    __shared__ float Bs[64 * 64];
    int tid = threadIdx.x;
    int base = blockIdx.x * 64;
#pragma unroll
    for (int i = 0; i < 8; i++) {
        int idx = tid + i * 128;
        int r = idx >> 4, c4 = (idx & 15) << 2;
        float4 v = make_float4(0.f, 0.f, 0.f, 0.f);
        if (base + r < NN) v = *(const float4*)(A + (size_t)(base + r) * 64 + c4);
        *(float4*)(As + r * 64 + c4) = v;
        *(float4*)(Bs + r * 64 + c4) = *(const float4*)(W + r * 64 + c4);
    }
    __syncthreads();
    int tx = tid & 15, ty = tid >> 4;
    int n0 = tx * 4, m0 = ty * 8;
    float acc[8][4];
#pragma unroll
    for (int i = 0; i < 8; i++) { acc[i][0] = 0.f; acc[i][1] = 0.f; acc[i][2] = 0.f; acc[i][3] = 0.f; }
#pragma unroll 2
    for (int k4 = 0; k4 < 16; k4++) {
        float4 b0 = *(float4*)(Bs + (k4 * 4 + 0) * 64 + n0);
        float4 b1 = *(float4*)(Bs + (k4 * 4 + 1) * 64 + n0);
        float4 b2 = *(float4*)(Bs + (k4 * 4 + 2) * 64 + n0);
        float4 b3 = *(float4*)(Bs + (k4 * 4 + 3) * 64 + n0);
#pragma unroll
        for (int i = 0; i < 8; i++) {
            float4 a = *(float4*)(As + (m0 + i) * 64 + k4 * 4);
            acc[i][0] += a.x * b0.x + a.y * b1.x + a.z * b2.x + a.w * b3.x;
            acc[i][1] += a.x * b0.y + a.y * b1.y + a.z * b2.y + a.w * b3.y;
            acc[i][2] += a.x * b0.z + a.y * b1.z + a.z * b2.z + a.w * b3.z;
            acc[i][3] += a.x * b0.w + a.y * b1.w + a.z * b2.w + a.w * b3.w;
        }
    }
    float4 bb = *(const float4*)(bias + n0);
    const bool do_att = (att != nullptr);
    int hh = n0 >> 3;
    float ci0 = 0.f, ci1 = 0.f, ci2 = 0.f, ci3 = 0.f;
    float cj0 = 0.f, cj1 = 0.f, cj2 = 0.f, cj3 = 0.f;
    if (do_att) {
        int o = n0 & 7;
        ci0 = att[hh * 16 + o];     ci1 = att[hh * 16 + o + 1];
        ci2 = att[hh * 16 + o + 2]; ci3 = att[hh * 16 + o + 3];
        cj0 = att[hh * 16 + 8 + o];     cj1 = att[hh * 16 + 8 + o + 1];
        cj2 = att[hh * 16 + 8 + o + 2]; cj3 = att[hh * 16 + 8 + o + 3];
    }
#pragma unroll
    for (int i = 0; i < 8; i++) {
        float4 o;
        o.x = acc[i][0] + bb.x;
        o.y = acc[i][1] + bb.y;
        o.z = acc[i][2] + bb.z;
        o.w = acc[i][3] + bb.w;
        if (do_relu) {
            o.x = fmaxf(o.x, 0.f); o.y = fmaxf(o.y, 0.f);
            o.z = fmaxf(o.z, 0.f); o.w = fmaxf(o.w, 0.f);
        }
        float pi = 0.f, pj = 0.f;
        if (do_att) {
            pi = o.x * ci0 + o.y * ci1 + o.z * ci2 + o.w * ci3;
            pj = o.x * cj0 + o.y * cj1 + o.z * cj2 + o.w * cj3;
            pi += __shfl_xor_sync(0xffffffffu, pi, 1);
            pj += __shfl_xor_sync(0xffffffffu, pj, 1);
        }
        int r = base + m0 + i;
        if (r < NN) {
            *(float4*)(C + (size_t)r * 64 + n0) = o;
            if (do_att && !(tx & 1)) {
                g_ai[r * 8 + hh] = pi;
                g_aj[r * 8 + hh] = pj;
            }
        }
    }
}

// ---------------- fused edge softmax + aggregation + ELU + LayerNorm ----------------
// One warp per destination node. Lane l owns feature cols (2l, 2l+1), head h = l>>2.
// Single pass (softmax shift-invariance; alphas are O(1) so exp never overflows):
// accumulate exp-sum + weighted features, then divide. Src indices are preloaded
// coalesced (one per lane) and broadcast by shuffle; inner loop 4-way unrolled so
// up to 8 gathers are in flight.
__global__ void __launch_bounds__(256) k_edge(const float* __restrict__ ob,
                                              const float* __restrict__ lg,
                                              const float* __restrict__ lb,
                                              float* __restrict__ out) {
    int n = (blockIdx.x * blockDim.x + threadIdx.x) >> 5;
    int lane = threadIdx.x & 31;
    if (n >= NN) return;
    int e0 = __ldg(&g_rowptr[n]), e1 = __ldg(&g_rowptr[n + 1]);
    int h = lane >> 2;
    float aih = __ldg(&g_ai[n * 8 + h]);

    float s = 0.f, ax = 0.f, ay = 0.f;
    const float2* hp2 = (const float2*)g_hp;
    for (int cb = e0; cb < e1; cb += 32) {
        int idx = cb + lane;
        int pre = (idx < e1) ? __ldg(&g_csrc[idx]) : 0;
        int cnt = min(32, e1 - cb);
        int j = 0;
        for (; j + 4 <= cnt; j += 4) {
            int s0 = __shfl_sync(0xffffffffu, pre, j);
            int s1 = __shfl_sync(0xffffffffu, pre, j + 1);
            int s2 = __shfl_sync(0xffffffffu, pre, j + 2);
            int s3 = __shfl_sync(0xffffffffu, pre, j + 3);
            float b0 = __ldg(&g_aj[s0 * 8 + h]);
            float b1 = __ldg(&g_aj[s1 * 8 + h]);
            float b2 = __ldg(&g_aj[s2 * 8 + h]);
            float b3 = __ldg(&g_aj[s3 * 8 + h]);
            float2 v0 = __ldg(&hp2[(size_t)s0 * 32 + lane]);
            float2 v1 = __ldg(&hp2[(size_t)s1 * 32 + lane]);
            float2 v2 = __ldg(&hp2[(size_t)s2 * 32 + lane]);
            float2 v3 = __ldg(&hp2[(size_t)s3 * 32 + lane]);
            float a0 = aih + b0; a0 = fmaxf(a0, 0.2f * a0); float w0 = __expf(a0);
            float a1 = aih + b1; a1 = fmaxf(a1, 0.2f * a1); float w1 = __expf(a1);
            float a2 = aih + b2; a2 = fmaxf(a2, 0.2f * a2); float w2 = __expf(a2);
            float a3 = aih + b3; a3 = fmaxf(a3, 0.2f * a3); float w3 = __expf(a3);
            s += w0 + w1 + w2 + w3;
            ax += v0.x * w0 + v1.x * w1 + v2.x * w2 + v3.x * w3;
            ay += v0.y * w0 + v1.y * w1 + v2.y * w2 + v3.y * w3;
        }
        for (; j < cnt; j++) {
            int sj = __shfl_sync(0xffffffffu, pre, j);
            float b = __ldg(&g_aj[sj * 8 + h]);
            float2 v = __ldg(&hp2[(size_t)sj * 32 + lane]);
            float a = aih + b; a = fmaxf(a, 0.2f * a); float w = __expf(a);
            s += w;
            ax += v.x * w;
            ay += v.y * w;
        }
    }

    float inv = 1.f / (s + 1e-16f);
    float vx = ax * inv + ob[2 * lane];
    float vy = ay * inv + ob[2 * lane + 1];
    vx = vx > 0.f ? vx : expm1f(vx);          // ELU
    vy = vy > 0.f ? vy : expm1f(vy);

    float sum = vx + vy, sq = vx * vx + vy * vy;
#pragma unroll
    for (int o = 16; o > 0; o >>= 1) {
        sum += __shfl_xor_sync(0xffffffffu, sum, o);
        sq  += __shfl_xor_sync(0xffffffffu, sq, o);
    }
    float mu = sum * (1.f / 64.f);
    float var = sq * (1.f / 64.f) - mu * mu;
    float rstd = rsqrtf(var + 1e-5f);
    float2 o2;
    o2.x = (vx - mu) * rstd * lg[2 * lane] + lb[2 * lane];
    o2.y = (vy - mu) * rstd * lg[2 * lane + 1] + lb[2 * lane + 1];
    ((float2*)out)[(size_t)n * 32 + lane] = o2;
}

// ---------------- launch ----------------
extern "C" void kernel_launch(void* const* d_in, const int* in_sizes, int n_in,
                              void* d_out, int out_size) {
    const float* x        = (const float*)d_in[0];
    const int*   ei       = (const int*)  d_in[1];
    const float* W_in     = (const float*)d_in[2];
    const float* b_in     = (const float*)d_in[3];
    const float* lin_w    = (const float*)d_in[4];
    const float* lin_b    = (const float*)d_in[5];
    const float* att      = (const float*)d_in[6];
    const float* out_bias = (const float*)d_in[7];
    const float* ln_g     = (const float*)d_in[8];
    const float* ln_b     = (const float*)d_in[9];
    float* out = (float*)d_out;
    const int* srcp = ei;        // edge_index[0]
    const int* dstp = ei + EE;   // edge_index[1]
    (void)n_in; (void)in_sizes; (void)out_size;

    void* p;
    cudaGetSymbolAddress(&p, g_h);   float* ph  = (float*)p;
    cudaGetSymbolAddress(&p, g_hp);  float* php = (float*)p;
    cudaGetSymbolAddress(&p, g_deg);
    cudaMemsetAsync(p, 0, NN * sizeof(int));

    // CSR by dst
    k_hist   <<<(EE + 255) / 256, 256>>>(dstp);
    k_scan   <<<1, 1024>>>();
    k_scatter<<<(EE + 255) / 256, 256>>>(srcp, dstp);

    int gblocks = (NN + 63) / 64;
    // input embedding: h = relu(x @ W_in + b_in)
    k_gemm<<<gblocks, 128>>>(x, W_in, b_in, ph, 1, nullptr);

    for (int l = 0; l < 5; l++) {
        k_gemm<<<gblocks, 128>>>(ph, lin_w + l * 64 * 64, lin_b + l * 64, php, 0,
                                 att + l * 128);
        k_edge<<<(NN + 7) / 8, 256>>>(out_bias + l * 64, ln_g + l * 64, ln_b + l * 64,
                                      (l == 4) ? out : ph);
    }
}

// round 4
// speedup vs baseline: 1.9733x; 1.1026x over previous
#include <cuda_runtime.h>
#include <cuda_fp16.h>
#include <math.h>

#define NN 50000
#define EE 800000
#define DD 64
#define HH 8

// ---------------- scratch (static device globals; no allocation) ----------------
__device__ float  g_h[NN * DD];      // node features fp32 (layer input)
__device__ __half g_hph[NN * DD];    // projected features, half (edge gather)
__device__ float  g_ai[NN * HH];     // per-node att dot, dst half
__device__ float  g_aj[NN * HH];     // per-node att dot, src half
__device__ int    g_deg[NN];
__device__ int    g_rowptr[NN + 1];
__device__ int    g_cursor[NN];
__device__ int    g_csrc[EE];        // CSR-by-dst: source node per slot
__device__ int    g_bsum[64];

// ---------------- CSR build ----------------
__global__ void k_hist(const int* __restrict__ dst) {
    int e = blockIdx.x * blockDim.x + threadIdx.x;
    if (e < EE) atomicAdd(&g_deg[dst[e]], 1);
}

__global__ void __launch_bounds__(1024) k_scan1() {
    __shared__ int ws[32];
    int i = blockIdx.x * 1024 + threadIdx.x;
    int lane = threadIdx.x & 31, w = threadIdx.x >> 5;
    int x = (i < NN) ? g_deg[i] : 0;
    int v = x;
#pragma unroll
    for (int o = 1; o < 32; o <<= 1) {
        int t = __shfl_up_sync(0xffffffffu, v, o);
        if (lane >= o) v += t;
    }
    if (lane == 31) ws[w] = v;
    __syncthreads();
    if (w == 0) {
        int t = ws[lane];
#pragma unroll
        for (int o = 1; o < 32; o <<= 1) {
            int u = __shfl_up_sync(0xffffffffu, t, o);
            if (lane >= o) t += u;
        }
        ws[lane] = t;
    }
    __syncthreads();
    int off = (w > 0) ? ws[w - 1] : 0;
    int incl = v + off;
    if (i < NN) g_rowptr[i] = incl - x;           // exclusive within block
    if (threadIdx.x == 1023) g_bsum[blockIdx.x] = incl;
}

// scan 49 block sums with one 64-thread block (two-warp smem scan)
__global__ void k_scan2(int nb) {
    __shared__ int sh[64];
    int t = threadIdx.x;
    int x = (t < nb) ? g_bsum[t] : 0;
    int lane = t & 31, w = t >> 5;
    int v = x;
#pragma unroll
    for (int o = 1; o < 32; o <<= 1) {
        int u = __shfl_up_sync(0xffffffffu, v, o);
        if (lane >= o) v += u;
    }
    if (lane == 31) sh[w] = v;
    __syncthreads();
    int add = (w == 1) ? sh[0] : 0;
    if (t < nb) g_bsum[t] = v + add - x;          // exclusive
}

__global__ void k_scan3() {
    int i = blockIdx.x * blockDim.x + threadIdx.x;
    if (i < NN) {
        int r = g_rowptr[i] + g_bsum[i >> 10];
        g_rowptr[i] = r;
        g_cursor[i] = r;
    }
    if (i == 0) g_rowptr[NN] = EE;
}

__global__ void k_scatter(const int* __restrict__ src, const int* __restrict__ dst) {
    int e = blockIdx.x * blockDim.x + threadIdx.x;
    if (e < EE) {
        int pos = atomicAdd(&g_cursor[dst[e]], 1);
        g_csrc[pos] = src[e];
    }
}

// ---------------- GEMM: C[N,64] = A[N,64] @ W[64,64] + bias ----------------
// 64x64 tile per 128-thread block; thread tile 8 rows x 4 cols.
// relu mode: write fp32 Cf with relu (input embedding).
// att mode: write half Ch + per-node-head attention dots ai/aj (no fp32 out).
__global__ void __launch_bounds__(128) k_gemm(const float* __restrict__ A,
                                              const float* __restrict__ W,
                                              const float* __restrict__ bias,
                                              float* __restrict__ Cf,
                                              __half* __restrict__ Ch,
                                              int do_relu,
                                              const float* __restrict__ att) {
    __shared__ float As[64 * 64];
    __shared__ float Bs[64 * 64];
    int tid = threadIdx.x;
    int base = blockIdx.x * 64;
#pragma unroll
    for (int i = 0; i < 8; i++) {
        int idx = tid + i * 128;
        int r = idx >> 4, c4 = (idx & 15) << 2;
        float4 v = make_float4(0.f, 0.f, 0.f, 0.f);
        if (base + r < NN) v = *(const float4*)(A + (size_t)(base + r) * 64 + c4);
        *(float4*)(As + r * 64 + c4) = v;
        *(float4*)(Bs + r * 64 + c4) = *(const float4*)(W + r * 64 + c4);
    }
    __syncthreads();
    int tx = tid & 15, ty = tid >> 4;
    int n0 = tx * 4, m0 = ty * 8;
    float acc[8][4];
#pragma unroll
    for (int i = 0; i < 8; i++) { acc[i][0] = 0.f; acc[i][1] = 0.f; acc[i][2] = 0.f; acc[i][3] = 0.f; }
#pragma unroll 2
    for (int k4 = 0; k4 < 16; k4++) {
        float4 b0 = *(float4*)(Bs + (k4 * 4 + 0) * 64 + n0);
        float4 b1 = *(float4*)(Bs + (k4 * 4 + 1) * 64 + n0);
        float4 b2 = *(float4*)(Bs + (k4 * 4 + 2) * 64 + n0);
        float4 b3 = *(float4*)(Bs + (k4 * 4 + 3) * 64 + n0);
#pragma unroll
        for (int i = 0; i < 8; i++) {
            float4 a = *(float4*)(As + (m0 + i) * 64 + k4 * 4);
            acc[i][0] += a.x * b0.x + a.y * b1.x + a.z * b2.x + a.w * b3.x;
            acc[i][1] += a.x * b0.y + a.y * b1.y + a.z * b2.y + a.w * b3.y;
            acc[i][2] += a.x * b0.z + a.y * b1.z + a.z * b2.z + a.w * b3.z;
            acc[i][3] += a.x * b0.w + a.y * b1.w + a.z * b2.w + a.w * b3.w;
        }
    }
    float4 bb = *(const float4*)(bias + n0);
    const bool do_att = (att != nullptr);
    int hh = n0 >> 3;
    float ci0 = 0.f, ci1 = 0.f, ci2 = 0.f, ci3 = 0.f;
    float cj0 = 0.f, cj1 = 0.f, cj2 = 0.f, cj3 = 0.f;
    if (do_att) {
        int o = n0 & 7;
        ci0 = att[hh * 16 + o];     ci1 = att[hh * 16 + o + 1];
        ci2 = att[hh * 16 + o + 2]; ci3 = att[hh * 16 + o + 3];
        cj0 = att[hh * 16 + 8 + o];     cj1 = att[hh * 16 + 8 + o + 1];
        cj2 = att[hh * 16 + 8 + o + 2]; cj3 = att[hh * 16 + 8 + o + 3];
    }
#pragma unroll
    for (int i = 0; i < 8; i++) {
        float4 o;
        o.x = acc[i][0] + bb.x;
        o.y = acc[i][1] + bb.y;
        o.z = acc[i][2] + bb.z;
        o.w = acc[i][3] + bb.w;
        int r = base + m0 + i;
        if (do_att) {
            float pi = o.x * ci0 + o.y * ci1 + o.z * ci2 + o.w * ci3;
            float pj = o.x * cj0 + o.y * cj1 + o.z * cj2 + o.w * cj3;
            pi += __shfl_xor_sync(0xffffffffu, pi, 1);
            pj += __shfl_xor_sync(0xffffffffu, pj, 1);
            if (r < NN) {
                __half2* hp = (__half2*)(Ch + (size_t)r * 64 + n0);
                hp[0] = __floats2half2_rn(o.x, o.y);
                hp[1] = __floats2half2_rn(o.z, o.w);
                if (!(tx & 1)) {
                    g_ai[r * 8 + hh] = pi;
                    g_aj[r * 8 + hh] = pj;
                }
            }
        } else if (r < NN) {
            if (do_relu) {
                o.x = fmaxf(o.x, 0.f); o.y = fmaxf(o.y, 0.f);
                o.z = fmaxf(o.z, 0.f); o.w = fmaxf(o.w, 0.f);
            }
            *(float4*)(Cf + (size_t)r * 64 + n0) = o;
        }
    }
}

// ---------------- fused edge softmax + aggregation + ELU + LayerNorm ----------------
// One warp per destination node. Lane l owns feature cols (2l, 2l+1), head h = l>>2.
// Single pass (shift-free softmax; alphas are O(1) so exp is safe). Src indices
// preloaded coalesced (one per lane), broadcast by shuffle, 4-way unrolled so up
// to 8 gathers are in flight. Features gathered in fp16 (half traffic).
__global__ void __launch_bounds__(256) k_edge(const float* __restrict__ ob,
                                              const float* __restrict__ lg,
                                              const float* __restrict__ lb,
                                              float* __restrict__ out) {
    int n = (blockIdx.x * blockDim.x + threadIdx.x) >> 5;
    int lane = threadIdx.x & 31;
    if (n >= NN) return;
    int e0 = __ldg(&g_rowptr[n]), e1 = __ldg(&g_rowptr[n + 1]);
    int h = lane >> 2;
    float aih = __ldg(&g_ai[n * 8 + h]);

    float s = 0.f, ax = 0.f, ay = 0.f;
    const __half2* hp2 = (const __half2*)g_hph;
    for (int cb = e0; cb < e1; cb += 32) {
        int idx = cb + lane;
        int pre = (idx < e1) ? __ldg(&g_csrc[idx]) : 0;
        int cnt = min(32, e1 - cb);
        int j = 0;
        for (; j + 4 <= cnt; j += 4) {
            int s0 = __shfl_sync(0xffffffffu, pre, j);
            int s1 = __shfl_sync(0xffffffffu, pre, j + 1);
            int s2 = __shfl_sync(0xffffffffu, pre, j + 2);
            int s3 = __shfl_sync(0xffffffffu, pre, j + 3);
            float b0 = __ldg(&g_aj[s0 * 8 + h]);
            float b1 = __ldg(&g_aj[s1 * 8 + h]);
            float b2 = __ldg(&g_aj[s2 * 8 + h]);
            float b3 = __ldg(&g_aj[s3 * 8 + h]);
            __half2 u0 = __ldg(&hp2[(size_t)s0 * 32 + lane]);
            __half2 u1 = __ldg(&hp2[(size_t)s1 * 32 + lane]);
            __half2 u2 = __ldg(&hp2[(size_t)s2 * 32 + lane]);
            __half2 u3 = __ldg(&hp2[(size_t)s3 * 32 + lane]);
            float2 v0 = __half22float2(u0);
            float2 v1 = __half22float2(u1);
            float2 v2 = __half22float2(u2);
            float2 v3 = __half22float2(u3);
            float a0 = aih + b0; a0 = fmaxf(a0, 0.2f * a0); float w0 = __expf(a0);
            float a1 = aih + b1; a1 = fmaxf(a1, 0.2f * a1); float w1 = __expf(a1);
            float a2 = aih + b2; a2 = fmaxf(a2, 0.2f * a2); float w2 = __expf(a2);
            float a3 = aih + b3; a3 = fmaxf(a3, 0.2f * a3); float w3 = __expf(a3);
            s += w0 + w1 + w2 + w3;
            ax += v0.x * w0 + v1.x * w1 + v2.x * w2 + v3.x * w3;
            ay += v0.y * w0 + v1.y * w1 + v2.y * w2 + v3.y * w3;
        }
        for (; j < cnt; j++) {
            int sj = __shfl_sync(0xffffffffu, pre, j);
            float b = __ldg(&g_aj[sj * 8 + h]);
            float2 v = __half22float2(__ldg(&hp2[(size_t)sj * 32 + lane]));
            float a = aih + b; a = fmaxf(a, 0.2f * a); float w = __expf(a);
            s += w;
            ax += v.x * w;
            ay += v.y * w;
        }
    }

    float inv = 1.f / (s + 1e-16f);
    float vx = ax * inv + ob[2 * lane];
    float vy = ay * inv + ob[2 * lane + 1];
    vx = vx > 0.f ? vx : expm1f(vx);          // ELU
    vy = vy > 0.f ? vy : expm1f(vy);

    float sum = vx + vy, sq = vx * vx + vy * vy;
#pragma unroll
    for (int o = 16; o > 0; o >>= 1) {
        sum += __shfl_xor_sync(0xffffffffu, sum, o);
        sq  += __shfl_xor_sync(0xffffffffu, sq, o);
    }
    float mu = sum * (1.f / 64.f);
    float var = sq * (1.f / 64.f) - mu * mu;
    float rstd = rsqrtf(var + 1e-5f);
    float2 o2;
    o2.x = (vx - mu) * rstd * lg[2 * lane] + lb[2 * lane];
    o2.y = (vy - mu) * rstd * lg[2 * lane + 1] + lb[2 * lane + 1];
    ((float2*)out)[(size_t)n * 32 + lane] = o2;
}

// ---------------- launch ----------------
extern "C" void kernel_launch(void* const* d_in, const int* in_sizes, int n_in,
                              void* d_out, int out_size) {
    const float* x        = (const float*)d_in[0];
    const int*   ei       = (const int*)  d_in[1];
    const float* W_in     = (const float*)d_in[2];
    const float* b_in     = (const float*)d_in[3];
    const float* lin_w    = (const float*)d_in[4];
    const float* lin_b    = (const float*)d_in[5];
    const float* att      = (const float*)d_in[6];
    const float* out_bias = (const float*)d_in[7];
    const float* ln_g     = (const float*)d_in[8];
    const float* ln_b     = (const float*)d_in[9];
    float* out = (float*)d_out;
    const int* srcp = ei;        // edge_index[0]
    const int* dstp = ei + EE;   // edge_index[1]
    (void)n_in; (void)in_sizes; (void)out_size;

    void* p;
    cudaGetSymbolAddress(&p, g_h);    float*  ph  = (float*)p;
    cudaGetSymbolAddress(&p, g_hph);  __half* phh = (__half*)p;
    cudaGetSymbolAddress(&p, g_deg);
    cudaMemsetAsync(p, 0, NN * sizeof(int));

    // CSR by dst
    const int nsb = (NN + 1023) / 1024;   // 49
    k_hist   <<<(EE + 255) / 256, 256>>>(dstp);
    k_scan1  <<<nsb, 1024>>>();
    k_scan2  <<<1, 64>>>(nsb);
    k_scan3  <<<(NN + 255) / 256, 256>>>();
    k_scatter<<<(EE + 255) / 256, 256>>>(srcp, dstp);

    int gblocks = (NN + 63) / 64;
    // input embedding: h = relu(x @ W_in + b_in)
    k_gemm<<<gblocks, 128>>>(x, W_in, b_in, ph, nullptr, 1, nullptr);

    for (int l = 0; l < 5; l++) {
        k_gemm<<<gblocks, 128>>>(ph, lin_w + l * 64 * 64, lin_b + l * 64,
                                 nullptr, phh, 0, att + l * 128);
        k_edge<<<(NN + 7) / 8, 256>>>(out_bias + l * 64, ln_g + l * 64, ln_b + l * 64,
                                      (l == 4) ? out : ph);
    }
}

// round 5
// speedup vs baseline: 2.1115x; 1.0700x over previous
#include <cuda_runtime.h>
#include <cuda_fp16.h>
#include <math.h>
#include <stdint.h>

#define NN 50000
#define EE 800000
#define DD 64
#define HH 8

// ---------------- scratch (static device globals; no allocation) ----------------
__device__ __half g_hh[NN * DD];     // node features, half (layer input)
__device__ __half g_hph[NN * DD];    // projected features, half (edge gather)
__device__ float  g_ai[NN * HH];     // per-node att dot, dst half (fp32)
__device__ __half g_ajh[NN * HH];    // per-node att dot, src half (fp16)
__device__ int    g_deg[NN];
__device__ int    g_rowptr[NN + 1];
__device__ int    g_cursor[NN];
__device__ int    g_csrc[EE];        // CSR-by-dst: source node per slot
__device__ int    g_bsum[64];

// ---------------- CSR build ----------------
__global__ void k_hist(const int* __restrict__ dst) {
    int e = blockIdx.x * blockDim.x + threadIdx.x;
    if (e < EE) atomicAdd(&g_deg[dst[e]], 1);
}

__global__ void __launch_bounds__(1024) k_scan1() {
    __shared__ int ws[32];
    int i = blockIdx.x * 1024 + threadIdx.x;
    int lane = threadIdx.x & 31, w = threadIdx.x >> 5;
    int x = (i < NN) ? g_deg[i] : 0;
    int v = x;
#pragma unroll
    for (int o = 1; o < 32; o <<= 1) {
        int t = __shfl_up_sync(0xffffffffu, v, o);
        if (lane >= o) v += t;
    }
    if (lane == 31) ws[w] = v;
    __syncthreads();
    if (w == 0) {
        int t = ws[lane];
#pragma unroll
        for (int o = 1; o < 32; o <<= 1) {
            int u = __shfl_up_sync(0xffffffffu, t, o);
            if (lane >= o) t += u;
        }
        ws[lane] = t;
    }
    __syncthreads();
    int off = (w > 0) ? ws[w - 1] : 0;
    int incl = v + off;
    if (i < NN) g_rowptr[i] = incl - x;           // exclusive within block
    if (threadIdx.x == 1023) g_bsum[blockIdx.x] = incl;
}

__global__ void k_scan2(int nb) {
    __shared__ int sh[64];
    int t = threadIdx.x;
    int x = (t < nb) ? g_bsum[t] : 0;
    int lane = t & 31, w = t >> 5;
    int v = x;
#pragma unroll
    for (int o = 1; o < 32; o <<= 1) {
        int u = __shfl_up_sync(0xffffffffu, v, o);
        if (lane >= o) v += u;
    }
    if (lane == 31) sh[w] = v;
    __syncthreads();
    int add = (w == 1) ? sh[0] : 0;
    if (t < nb) g_bsum[t] = v + add - x;          // exclusive
}

__global__ void k_scan3() {
    int i = blockIdx.x * blockDim.x + threadIdx.x;
    if (i < NN) {
        int r = g_rowptr[i] + g_bsum[i >> 10];
        g_rowptr[i] = r;
        g_cursor[i] = r;
    }
    if (i == 0) g_rowptr[NN] = EE;
}

__global__ void k_scatter(const int* __restrict__ src, const int* __restrict__ dst) {
    int e = blockIdx.x * blockDim.x + threadIdx.x;
    if (e < EE) {
        int pos = atomicAdd(&g_cursor[dst[e]], 1);
        g_csrc[pos] = src[e];
    }
}

// ---------------- tensor-core GEMM: C[N,64] = A[N,64] @ W[64,64] + bias ----------------
// mma.sync m16n8k16 f16xf16->f32. Block = 128 thr (4 warps), 64 rows per block,
// warp tile m16 x n64 x k64. A from fp16 (Ah) or fp32 (Af, converted). Output half.
__device__ __forceinline__ uint32_t smem_u32(const void* p) {
    return (uint32_t)__cvta_generic_to_shared(p);
}

#define LDSM_X4(r0, r1, r2, r3, addr) \
    asm volatile("ldmatrix.sync.aligned.m8n8.x4.shared.b16 {%0,%1,%2,%3}, [%4];" \
        : "=r"(r0), "=r"(r1), "=r"(r2), "=r"(r3) : "r"(addr))

#define LDSM_X4_T(r0, r1, r2, r3, addr) \
    asm volatile("ldmatrix.sync.aligned.m8n8.x4.trans.shared.b16 {%0,%1,%2,%3}, [%4];" \
        : "=r"(r0), "=r"(r1), "=r"(r2), "=r"(r3) : "r"(addr))

#define MMA16816(c, a0, a1, a2, a3, b0, b1) \
    asm volatile("mma.sync.aligned.m16n8k16.row.col.f32.f16.f16.f32 " \
        "{%0,%1,%2,%3}, {%4,%5,%6,%7}, {%8,%9}, {%0,%1,%2,%3};" \
        : "+f"(c[0]), "+f"(c[1]), "+f"(c[2]), "+f"(c[3]) \
        : "r"(a0), "r"(a1), "r"(a2), "r"(a3), "r"(b0), "r"(b1))

#define SMS 72   // smem row stride in halves (64 + 8 pad -> 4-bank shift per row)

__global__ void __launch_bounds__(128) k_gemm_h(const __half* __restrict__ Ah,
                                                const float* __restrict__ Af,
                                                const float* __restrict__ W,
                                                const float* __restrict__ bias,
                                                __half* __restrict__ C,
                                                int do_relu) {
    __shared__ __half As[64 * SMS];
    __shared__ __half Bs[64 * SMS];
    int tid = threadIdx.x;
    int base = blockIdx.x * 64;
#pragma unroll
    for (int i = 0; i < 4; i++) {
        int chunk = tid + i * 128;            // 0..511
        int r = chunk >> 3, c = (chunk & 7) * 8;
        // W (fp32 [k][n]) -> Bs half
        float4 w0 = *(const float4*)(W + r * 64 + c);
        float4 w1 = *(const float4*)(W + r * 64 + c + 4);
        __half2* db = (__half2*)(Bs + r * SMS + c);
        db[0] = __floats2half2_rn(w0.x, w0.y);
        db[1] = __floats2half2_rn(w0.z, w0.w);
        db[2] = __floats2half2_rn(w1.x, w1.y);
        db[3] = __floats2half2_rn(w1.z, w1.w);
        // A -> As half
        int gr = base + r;
        if (Ah) {
            uint4 v = make_uint4(0u, 0u, 0u, 0u);
            if (gr < NN) v = *(const uint4*)(Ah + (size_t)gr * 64 + c);
            *(uint4*)(As + r * SMS + c) = v;
        } else {
            float4 a0 = make_float4(0.f, 0.f, 0.f, 0.f), a1 = a0;
            if (gr < NN) {
                a0 = *(const float4*)(Af + (size_t)gr * 64 + c);
                a1 = *(const float4*)(Af + (size_t)gr * 64 + c + 4);
            }
            __half2* da = (__half2*)(As + r * SMS + c);
            da[0] = __floats2half2_rn(a0.x, a0.y);
            da[1] = __floats2half2_rn(a0.z, a0.w);
            da[2] = __floats2half2_rn(a1.x, a1.y);
            da[3] = __floats2half2_rn(a1.z, a1.w);
        }
    }
    __syncthreads();

    int warp = tid >> 5, lane = tid & 31;
    int m0 = warp * 16;
    float acc[8][4];
#pragma unroll
    for (int n = 0; n < 8; n++)
#pragma unroll
        for (int q = 0; q < 4; q++) acc[n][q] = 0.f;

#pragma unroll
    for (int kk = 0; kk < 4; kk++) {
        uint32_t a0, a1, a2, a3;
        uint32_t aaddr = smem_u32(As + (m0 + (lane & 15)) * SMS + kk * 16 + (lane >> 4) * 8);
        LDSM_X4(a0, a1, a2, a3, aaddr);
#pragma unroll
        for (int np = 0; np < 4; np++) {
            uint32_t b0, b1, b2, b3;
            uint32_t baddr = smem_u32(Bs + (kk * 16 + (lane & 15)) * SMS + np * 16 + (lane >> 4) * 8);
            LDSM_X4_T(b0, b1, b2, b3, baddr);
            MMA16816(acc[2 * np],     a0, a1, a2, a3, b0, b1);
            MMA16816(acc[2 * np + 1], a0, a1, a2, a3, b2, b3);
        }
    }

    int qr = lane >> 2, qc = (lane & 3) * 2;
    int r0 = base + m0 + qr, r1 = r0 + 8;
#pragma unroll
    for (int n = 0; n < 8; n++) {
        int col = n * 8 + qc;
        float2 bb = *(const float2*)(bias + col);
        float x0 = acc[n][0] + bb.x, y0 = acc[n][1] + bb.y;
        float x1 = acc[n][2] + bb.x, y1 = acc[n][3] + bb.y;
        if (do_relu) {
            x0 = fmaxf(x0, 0.f); y0 = fmaxf(y0, 0.f);
            x1 = fmaxf(x1, 0.f); y1 = fmaxf(y1, 0.f);
        }
        if (r0 < NN) *(__half2*)(C + (size_t)r0 * 64 + col) = __floats2half2_rn(x0, y0);
        if (r1 < NN) *(__half2*)(C + (size_t)r1 * 64 + col) = __floats2half2_rn(x1, y1);
    }
}

// ---------------- per-node attention dot products (reads fp16 hp) ----------------
__global__ void k_attdot(const float* __restrict__ att) {
    int idx = blockIdx.x * blockDim.x + threadIdx.x;
    if (idx >= NN * HH) return;
    int n = idx >> 3, h = idx & 7;
    uint4 v = *(const uint4*)(g_hph + (size_t)n * 64 + h * 8);
    __half2* hv = (__half2*)&v;
    float2 f0 = __half22float2(hv[0]);
    float2 f1 = __half22float2(hv[1]);
    float2 f2 = __half22float2(hv[2]);
    float2 f3 = __half22float2(hv[3]);
    const float4* a4 = (const float4*)(att + h * 16);
    float4 A0 = a4[0], A1 = a4[1], A2 = a4[2], A3 = a4[3];
    float ai = f0.x * A0.x + f0.y * A0.y + f1.x * A0.z + f1.y * A0.w +
               f2.x * A1.x + f2.y * A1.y + f3.x * A1.z + f3.y * A1.w;
    float aj = f0.x * A2.x + f0.y * A2.y + f1.x * A2.z + f1.y * A2.w +
               f2.x * A3.x + f2.y * A3.y + f3.x * A3.z + f3.y * A3.w;
    g_ai[idx]  = ai;
    g_ajh[idx] = __float2half(aj);
}

// ---------------- fused edge softmax + aggregation + ELU + LayerNorm ----------------
// One warp per destination node. Lane l owns cols (2l,2l+1), head h = l>>2.
// Single-pass shift-free softmax; src indices preloaded coalesced + shuffled;
// 4-way unrolled gathers (fp16 features + fp16 aj).
__global__ void __launch_bounds__(256) k_edge(const float* __restrict__ ob,
                                              const float* __restrict__ lg,
                                              const float* __restrict__ lb,
                                              float* __restrict__ outf,
                                              __half* __restrict__ outh) {
    int n = (blockIdx.x * blockDim.x + threadIdx.x) >> 5;
    int lane = threadIdx.x & 31;
    if (n >= NN) return;
    int e0 = __ldg(&g_rowptr[n]), e1 = __ldg(&g_rowptr[n + 1]);
    int h = lane >> 2;
    float aih = __ldg(&g_ai[n * 8 + h]);

    float s = 0.f, ax = 0.f, ay = 0.f;
    const __half2* hp2 = (const __half2*)g_hph;
    for (int cb = e0; cb < e1; cb += 32) {
        int idx = cb + lane;
        int pre = (idx < e1) ? __ldg(&g_csrc[idx]) : 0;
        int cnt = min(32, e1 - cb);
        int j = 0;
        for (; j + 4 <= cnt; j += 4) {
            int s0 = __shfl_sync(0xffffffffu, pre, j);
            int s1 = __shfl_sync(0xffffffffu, pre, j + 1);
            int s2 = __shfl_sync(0xffffffffu, pre, j + 2);
            int s3 = __shfl_sync(0xffffffffu, pre, j + 3);
            float b0 = __half2float(__ldg(&g_ajh[s0 * 8 + h]));
            float b1 = __half2float(__ldg(&g_ajh[s1 * 8 + h]));
            float b2 = __half2float(__ldg(&g_ajh[s2 * 8 + h]));
            float b3 = __half2float(__ldg(&g_ajh[s3 * 8 + h]));
            __half2 u0 = __ldg(&hp2[(size_t)s0 * 32 + lane]);
            __half2 u1 = __ldg(&hp2[(size_t)s1 * 32 + lane]);
            __half2 u2 = __ldg(&hp2[(size_t)s2 * 32 + lane]);
            __half2 u3 = __ldg(&hp2[(size_t)s3 * 32 + lane]);
            float2 v0 = __half22float2(u0);
            float2 v1 = __half22float2(u1);
            float2 v2 = __half22float2(u2);
            float2 v3 = __half22float2(u3);
            float a0 = aih + b0; a0 = fmaxf(a0, 0.2f * a0); float w0 = __expf(a0);
            float a1 = aih + b1; a1 = fmaxf(a1, 0.2f * a1); float w1 = __expf(a1);
            float a2 = aih + b2; a2 = fmaxf(a2, 0.2f * a2); float w2 = __expf(a2);
            float a3 = aih + b3; a3 = fmaxf(a3, 0.2f * a3); float w3 = __expf(a3);
            s += w0 + w1 + w2 + w3;
            ax += v0.x * w0 + v1.x * w1 + v2.x * w2 + v3.x * w3;
            ay += v0.y * w0 + v1.y * w1 + v2.y * w2 + v3.y * w3;
        }
        for (; j < cnt; j++) {
            int sj = __shfl_sync(0xffffffffu, pre, j);
            float b = __half2float(__ldg(&g_ajh[sj * 8 + h]));
            float2 v = __half22float2(__ldg(&hp2[(size_t)sj * 32 + lane]));
            float a = aih + b; a = fmaxf(a, 0.2f * a); float w = __expf(a);
            s += w;
            ax += v.x * w;
            ay += v.y * w;
        }
    }

    float inv = 1.f / (s + 1e-16f);
    float vx = ax * inv + ob[2 * lane];
    float vy = ay * inv + ob[2 * lane + 1];
    vx = vx > 0.f ? vx : expm1f(vx);          // ELU
    vy = vy > 0.f ? vy : expm1f(vy);

    float sum = vx + vy, sq = vx * vx + vy * vy;
#pragma unroll
    for (int o = 16; o > 0; o >>= 1) {
        sum += __shfl_xor_sync(0xffffffffu, sum, o);
        sq  += __shfl_xor_sync(0xffffffffu, sq, o);
    }
    float mu = sum * (1.f / 64.f);
    float var = sq * (1.f / 64.f) - mu * mu;
    float rstd = rsqrtf(var + 1e-5f);
    float ox = (vx - mu) * rstd * lg[2 * lane] + lb[2 * lane];
    float oy = (vy - mu) * rstd * lg[2 * lane + 1] + lb[2 * lane + 1];
    if (outf) {
        float2 o2; o2.x = ox; o2.y = oy;
        ((float2*)outf)[(size_t)n * 32 + lane] = o2;
    } else {
        ((__half2*)outh)[(size_t)n * 32 + lane] = __floats2half2_rn(ox, oy);
    }
}

// ---------------- launch ----------------
extern "C" void kernel_launch(void* const* d_in, const int* in_sizes, int n_in,
                              void* d_out, int out_size) {
    const float* x        = (const float*)d_in[0];
    const int*   ei       = (const int*)  d_in[1];
    const float* W_in     = (const float*)d_in[2];
    const float* b_in     = (const float*)d_in[3];
    const float* lin_w    = (const float*)d_in[4];
    const float* lin_b    = (const float*)d_in[5];
    const float* att      = (const float*)d_in[6];
    const float* out_bias = (const float*)d_in[7];
    const float* ln_g     = (const float*)d_in[8];
    const float* ln_b     = (const float*)d_in[9];
    float* out = (float*)d_out;
    const int* srcp = ei;        // edge_index[0]
    const int* dstp = ei + EE;   // edge_index[1]
    (void)n_in; (void)in_sizes; (void)out_size;

    void* p;
    cudaGetSymbolAddress(&p, g_hh);   __half* phh  = (__half*)p;
    cudaGetSymbolAddress(&p, g_hph);  __half* phph = (__half*)p;
    cudaGetSymbolAddress(&p, g_deg);
    cudaMemsetAsync(p, 0, NN * sizeof(int));

    // CSR by dst
    const int nsb = (NN + 1023) / 1024;   // 49
    k_hist   <<<(EE + 255) / 256, 256>>>(dstp);
    k_scan1  <<<nsb, 1024>>>();
    k_scan2  <<<1, 64>>>(nsb);
    k_scan3  <<<(NN + 255) / 256, 256>>>();
    k_scatter<<<(EE + 255) / 256, 256>>>(srcp, dstp);

    int gblocks = (NN + 63) / 64;
    // input embedding: h = relu(x @ W_in + b_in), stored fp16
    k_gemm_h<<<gblocks, 128>>>(nullptr, x, W_in, b_in, phh, 1);

    for (int l = 0; l < 5; l++) {
        k_gemm_h<<<gblocks, 128>>>(phh, nullptr, lin_w + l * 64 * 64, lin_b + l * 64,
                                   phph, 0);
        k_attdot<<<(NN * 8 + 255) / 256, 256>>>(att + l * 128);
        k_edge<<<(NN + 7) / 8, 256>>>(out_bias + l * 64, ln_g + l * 64, ln_b + l * 64,
                                      (l == 4) ? out : nullptr,
                                      (l == 4) ? nullptr : phh);
    }
}